// round 10
// baseline (speedup 1.0000x reference)
#include <cuda_runtime.h>
#include <cuda_bf16.h>
#include <math.h>
#include <stdint.h>
#include <stddef.h>

#define N1 16384
#define N2 4096
#define DM 256
#define ATTD 128
#define NE 4
#define KT 64
#define NKT (N2 / KT)

// ------------------------- static device scratch -------------------------
__device__ float g_ctx[N1 * DM];
__device__ float g_Vp[N2 * DM];
__device__ float g_snn2[N2 * DM];
__device__ float g_part1[256 * DM];
__device__ float g_part2[128 * DM];
__device__ float g_part2b[128 * DM];
__device__ float g_poolpart[128 * DM];
__device__ float g_logit[N2];
__device__ float g_a[N2];
__device__ float g_r1[N1];
__device__ float g_r2[N2];
__device__ float g_w[NE];
__device__ float g_invns;
__device__ float g_m2[DM];
__device__ float g_pf[DM];
// bf16 operands
__device__ __nv_bfloat16 g_Qh[N1 * DM];
__device__ __nv_bfloat16 g_Kh[N2 * DM];
__device__ __nv_bfloat16 g_VTh[DM * N2];     // [d][key]
__device__ __nv_bfloat16 g_x1h[N1 * DM];
__device__ __nv_bfloat16 g_x2h[N2 * DM];
__device__ __nv_bfloat16 g_x2rh[N2 * DM];
// transposed bf16 weights [n][k]
__device__ __nv_bfloat16 g_wqt[DM * DM];
__device__ __nv_bfloat16 g_wkt[DM * DM];
__device__ __nv_bfloat16 g_wvt[DM * DM];
__device__ __nv_bfloat16 g_w2t[DM * DM];

// ------------------------- helpers -------------------------
__device__ __forceinline__ uint32_t smem_u32(const void* p) {
    uint32_t a;
    asm("{ .reg .u64 t; cvta.to.shared.u64 t, %1; cvt.u32.u64 %0, t; }" : "=r"(a) : "l"(p));
    return a;
}
__device__ __forceinline__ uint32_t pack_bf2(float a, float b) {
    __nv_bfloat162 t = __floats2bfloat162_rn(a, b);
    return *reinterpret_cast<uint32_t*>(&t);
}
__device__ __forceinline__ void ldsm_x4(uint32_t& r0, uint32_t& r1, uint32_t& r2, uint32_t& r3, uint32_t addr) {
    asm volatile("ldmatrix.sync.aligned.m8n8.x4.shared.b16 {%0,%1,%2,%3}, [%4];"
        : "=r"(r0), "=r"(r1), "=r"(r2), "=r"(r3) : "r"(addr));
}
__device__ __forceinline__ void mma16816(float* c, uint32_t a0, uint32_t a1, uint32_t a2, uint32_t a3,
                                         uint32_t b0, uint32_t b1) {
    asm volatile("mma.sync.aligned.m16n8k16.row.col.f32.bf16.bf16.f32 "
        "{%0,%1,%2,%3}, {%4,%5,%6,%7}, {%8,%9}, {%0,%1,%2,%3};"
        : "+f"(c[0]), "+f"(c[1]), "+f"(c[2]), "+f"(c[3])
        : "r"(a0), "r"(a1), "r"(a2), "r"(a3), "r"(b0), "r"(b1));
}
__device__ __forceinline__ void cp16(uint32_t s, const void* g) {
    asm volatile("cp.async.cg.shared.global [%0], [%1], 16;" :: "r"(s), "l"(g));
}
#define CP_COMMIT() asm volatile("cp.async.commit_group;" ::: "memory")
#define CP_WAIT1()  asm volatile("cp.async.wait_group 1;" ::: "memory")

// ------------------------- row RMS norms -------------------------
__global__ void k_rownorm(const float* __restrict__ x, int which) {
    int warp = threadIdx.x >> 5, lane = threadIdx.x & 31;
    int row = blockIdx.x * 8 + warp;
    const float* p = x + (size_t)row * DM;
    float s = 0.f;
#pragma unroll
    for (int i = 0; i < 8; i++) { float v = p[lane + i * 32]; s += v * v; }
#pragma unroll
    for (int o = 16; o > 0; o >>= 1) s += __shfl_xor_sync(0xffffffffu, s, o);
    if (lane == 0) (which ? g_r2 : g_r1)[row] = rsqrtf(s * (1.0f / DM) + 1e-6f);
}

// column partial sums — wide grids (proven correct by R8/R9 identical-error logic)
__global__ void k_colsum(const float* __restrict__ x, int rpb, int dst) {
    const float* src = x ? x : g_snn2;
    int d = threadIdx.x;
    const float* p = src + (size_t)blockIdx.x * rpb * DM + d;
    float s = 0.f;
#pragma unroll 4
    for (int i = 0; i < rpb; i++) s += p[(size_t)i * DM];
    float* o = (dst == 0) ? g_part1 : (dst == 1) ? g_part2 : g_part2b;
    o[blockIdx.x * DM + d] = s;
}

__global__ void k_gate(const float* __restrict__ sim, const float* __restrict__ gates) {
    __shared__ float red[256];
    __shared__ float sc[NE];
    int d = threadIdx.x;
    float s1 = 0.f, s2 = 0.f;
    for (int i = 0; i < 256; i++) s1 += g_part1[i * DM + d];
    for (int i = 0; i < 128; i++) s2 += g_part2[i * DM + d];
    float f = 0.5f * (s1 * (1.0f / N1) + s2 * (1.0f / N2));
    red[d] = f * f; __syncthreads();
    for (int o = 128; o > 0; o >>= 1) { if (d < o) red[d] += red[d + o]; __syncthreads(); }
    float fn = f * rsqrtf(red[0] + 1e-8f);
    for (int e = 0; e < NE; e++) {
        float sv = sim[e * DM + d];
        __syncthreads();
        red[d] = sv * sv; __syncthreads();
        for (int o = 128; o > 0; o >>= 1) { if (d < o) red[d] += red[d + o]; __syncthreads(); }
        float invn = rsqrtf(red[0] + 1e-8f);
        __syncthreads();
        red[d] = fn * sv; __syncthreads();
        for (int o = 128; o > 0; o >>= 1) { if (d < o) red[d] += red[d + o]; __syncthreads(); }
        if (d == 0) sc[e] = red[0] * invn;
    }
    __syncthreads();
    if (d == 0) {
        float s[NE] = { sc[0], sc[1], sc[2], sc[3] };
        int am = 0;
        for (int e = 1; e < NE; e++) if (s[e] > s[am]) am = e;
        float second = -INFINITY;
        for (int e = 0; e < NE; e++) if (e != am) second = fmaxf(second, s[e]);
        int cnt = 0;
        for (int e = 0; e < NE; e++) {
            bool keep = (s[e] >= second) && (s[e] > gates[e]);
            float w = keep ? s[e] : 0.0f;
            g_w[e] = w;
            if (w > 0.f) cnt++;
        }
        g_invns = 1.0f / fmaxf((float)cnt, 1.0f);
    }
}

// ------------------------- bf16 conversions -------------------------
__global__ void k_cvt_x(const float* __restrict__ src, __nv_bfloat16* __restrict__ dst,
                        const float* __restrict__ rms, const float* __restrict__ gv) {
    size_t i = (size_t)(blockIdx.x * 256 + threadIdx.x) * 8;
    int row = (int)(i >> 8), c0 = (int)(i & 255);
    float r = rms ? rms[row] : 1.0f;
    float4 a = *(const float4*)(src + i), b = *(const float4*)(src + i + 4);
    float g[8];
#pragma unroll
    for (int k = 0; k < 8; k++) g[k] = gv ? gv[c0 + k] : 1.0f;
    *(uint4*)(dst + i) = make_uint4(
        pack_bf2(a.x * r * g[0], a.y * r * g[1]), pack_bf2(a.z * r * g[2], a.w * r * g[3]),
        pack_bf2(b.x * r * g[4], b.y * r * g[5]), pack_bf2(b.z * r * g[6], b.w * r * g[7]));
}

__global__ void k_cvt_wt(const float* __restrict__ W, __nv_bfloat16* __restrict__ dhi) {
    int idx = blockIdx.x * 256 + threadIdx.x;
    int k = idx >> 8, n = idx & 255;
    dhi[n * DM + k] = __float2bfloat16_rn(W[k * DM + n]);
}

__global__ void k_cvt_tr() {
    __shared__ float s[64][65];
    int n0 = blockIdx.x * 64, d0 = blockIdx.y * 64;
    int tid = threadIdx.x;
#pragma unroll
    for (int i = 0; i < 16; i++) {
        int e = tid + i * 256;
        int n = e >> 6, d = e & 63;
        s[n][d] = g_Vp[(size_t)(n0 + n) * DM + d0 + d];
    }
    __syncthreads();
#pragma unroll
    for (int i = 0; i < 16; i++) {
        int e = tid + i * 256;
        int d = e >> 6, n = e & 63;
        g_VTh[(size_t)(d0 + d) * N2 + n0 + n] = __float2bfloat16_rn(s[n][d]);
    }
}

// ------------------------- HMMA projection GEMM (verified) -------------------------
#define HG_AROW 528
#define HG_WOFF 67584
#define HG_SMEM 135168

__global__ __launch_bounds__(256, 1) void k_hgemm(
    const __nv_bfloat16* __restrict__ A, const __nv_bfloat16* __restrict__ Wt,
    const float* __restrict__ bias, int mode)
{
    extern __shared__ char sm[];
    const uint32_t sb = smem_u32(sm);
    const int tid = threadIdx.x, warp = tid >> 5, lane = tid & 31;
    const int r0 = blockIdx.y * 128, nb = blockIdx.x * 128;

#pragma unroll
    for (int i = 0; i < 16; i++) {
        int c = tid + i * 256;
        int r = c >> 5, q = c & 31;
        *(uint4*)(sm + r * HG_AROW + q * 16) = *(const uint4*)(A + (size_t)(r0 + r) * DM + q * 8);
        *(uint4*)(sm + HG_WOFF + r * HG_AROW + q * 16) = *(const uint4*)(Wt + (size_t)(nb + r) * DM + q * 8);
    }
    __syncthreads();

    const int wm = warp >> 1, wn = warp & 1;
    const uint32_t lsel = lane & 15;
    const uint32_t khalf = (lane >> 4) * 16;
    const uint32_t abase = sb + (wm * 32 + lsel) * HG_AROW + khalf;
    const uint32_t bbase = sb + HG_WOFF + (wn * 64 + lsel) * HG_AROW + khalf;

    float acc[2][8][4];
#pragma unroll
    for (int m = 0; m < 2; m++)
#pragma unroll
        for (int n = 0; n < 8; n++)
#pragma unroll
            for (int c = 0; c < 4; c++) acc[m][n][c] = 0.f;

#pragma unroll 4
    for (int ks = 0; ks < 16; ks++) {
        uint32_t a[2][4];
        ldsm_x4(a[0][0], a[0][1], a[0][2], a[0][3], abase + ks * 32);
        ldsm_x4(a[1][0], a[1][1], a[1][2], a[1][3], abase + 16 * HG_AROW + ks * 32);
#pragma unroll
        for (int ng = 0; ng < 4; ng++) {
            uint32_t b0, b1, b2, b3;
            ldsm_x4(b0, b1, b2, b3, bbase + ng * 16 * HG_AROW + ks * 32);
#pragma unroll
            for (int m = 0; m < 2; m++) {
                mma16816(acc[m][ng * 2], a[m][0], a[m][1], a[m][2], a[m][3], b0, b2);
                mma16816(acc[m][ng * 2 + 1], a[m][0], a[m][1], a[m][2], a[m][3], b1, b3);
            }
        }
    }

    const int rb = r0 + wm * 32 + (lane >> 2);
    const int cb = nb + wn * 64 + (lane & 3) * 2;
#pragma unroll
    for (int m = 0; m < 2; m++)
#pragma unroll
        for (int nf = 0; nf < 8; nf++) {
            int row = rb + m * 16, col = cb + nf * 8;
            float* c = acc[m][nf];
            if (mode == 0) {
                *(uint32_t*)(g_Qh + (size_t)row * DM + col) = pack_bf2(c[0], c[1]);
                *(uint32_t*)(g_Qh + (size_t)(row + 8) * DM + col) = pack_bf2(c[2], c[3]);
            } else if (mode == 1) {
                *(uint32_t*)(g_Kh + (size_t)row * DM + col) = pack_bf2(c[0], c[1]);
                *(uint32_t*)(g_Kh + (size_t)(row + 8) * DM + col) = pack_bf2(c[2], c[3]);
            } else if (mode == 2) {
                *(float2*)(g_Vp + (size_t)row * DM + col) = make_float2(c[0], c[1]);
                *(float2*)(g_Vp + (size_t)(row + 8) * DM + col) = make_float2(c[2], c[3]);
            } else {
                float bb0 = bias[col], bb1 = bias[col + 1];
                float v0 = c[0] + bb0, v1 = c[1] + bb1, v2 = c[2] + bb0, v3 = c[3] + bb1;
                v0 = v0 > 0.f ? v0 : (__expf(v0) - 1.f);
                v1 = v1 > 0.f ? v1 : (__expf(v1) - 1.f);
                v2 = v2 > 0.f ? v2 : (__expf(v2) - 1.f);
                v3 = v3 > 0.f ? v3 : (__expf(v3) - 1.f);
                *(float2*)(g_snn2 + (size_t)row * DM + col) = make_float2(v0, v1);
                *(float2*)(g_snn2 + (size_t)(row + 8) * DM + col) = make_float2(v2, v3);
            }
        }
}

// ------------------------- DAMISL logits / softmax / pool -------------------------
__global__ __launch_bounds__(256) void k_hlogit(
    const float* __restrict__ x2, const float* __restrict__ va,
    const float* __restrict__ ua, const float* __restrict__ wa)
{
    __shared__ float Xs[32][65];
    __shared__ float Vt[32][128];
    __shared__ float Ut[32][128];
    __shared__ float was[128];
    __shared__ float red[64 * 17];
    const int tid = threadIdx.x, tx = tid & 15, ty = tid >> 4;
    const int r0 = blockIdx.x * 64;
    if (tid < 128) was[tid] = wa[tid];
    float aV[4][8], aU[4][8];
#pragma unroll
    for (int i = 0; i < 4; i++)
#pragma unroll
        for (int j = 0; j < 8; j++) { aV[i][j] = 0.f; aU[i][j] = 0.f; }
    for (int kc = 0; kc < DM; kc += 32) {
#pragma unroll
        for (int it = 0; it < 2; it++) {
            int idx = tid + it * 256;
            int m = idx >> 3, q = idx & 7;
            float4 v = *(const float4*)(x2 + (size_t)(r0 + m) * DM + kc + q * 4);
            Xs[q * 4 + 0][m] = v.x; Xs[q * 4 + 1][m] = v.y;
            Xs[q * 4 + 2][m] = v.z; Xs[q * 4 + 3][m] = v.w;
        }
#pragma unroll
        for (int it = 0; it < 4; it++) {
            int idx = tid + it * 256;
            int kr = idx >> 5, q = idx & 31;
            *(float4*)&Vt[kr][q * 4] = *(const float4*)(va + (size_t)(kc + kr) * ATTD + q * 4);
            *(float4*)&Ut[kr][q * 4] = *(const float4*)(ua + (size_t)(kc + kr) * ATTD + q * 4);
        }
        __syncthreads();
#pragma unroll 4
        for (int kk = 0; kk < 32; kk++) {
            float a[4];
#pragma unroll
            for (int i = 0; i < 4; i++) a[i] = Xs[kk][ty * 4 + i];
            float4 v0 = *(const float4*)&Vt[kk][tx * 8];
            float4 v1 = *(const float4*)&Vt[kk][tx * 8 + 4];
            float4 u0 = *(const float4*)&Ut[kk][tx * 8];
            float4 u1 = *(const float4*)&Ut[kk][tx * 8 + 4];
            float vb[8] = { v0.x, v0.y, v0.z, v0.w, v1.x, v1.y, v1.z, v1.w };
            float ub[8] = { u0.x, u0.y, u0.z, u0.w, u1.x, u1.y, u1.z, u1.w };
#pragma unroll
            for (int i = 0; i < 4; i++)
#pragma unroll
                for (int j = 0; j < 8; j++) { aV[i][j] += a[i] * vb[j]; aU[i][j] += a[i] * ub[j]; }
        }
        __syncthreads();
    }
#pragma unroll
    for (int i = 0; i < 4; i++) {
        float rp = 0.f;
#pragma unroll
        for (int j = 0; j < 8; j++) {
            float h = tanhf(aV[i][j]) * (1.0f / (1.0f + __expf(-aU[i][j])));
            rp += h * was[tx * 8 + j];
        }
        red[(ty * 4 + i) * 17 + tx] = rp;
    }
    __syncthreads();
    if (tid < 64) {
        float s = 0.f;
#pragma unroll
        for (int t = 0; t < 16; t++) s += red[tid * 17 + t];
        g_logit[r0 + tid] = s;
    }
}

__global__ void k_attnnorm() {
    __shared__ float red[256];
    int t = threadIdx.x;
    float lm = -INFINITY;
    for (int i = t; i < N2; i += 256) lm = fmaxf(lm, g_logit[i]);
    red[t] = lm; __syncthreads();
    for (int o = 128; o > 0; o >>= 1) { if (t < o) red[t] = fmaxf(red[t], red[t + o]); __syncthreads(); }
    float mx = red[0];
    __syncthreads();
    float ls = 0.f;
    for (int i = t; i < N2; i += 256) ls += __expf(g_logit[i] - mx);
    red[t] = ls; __syncthreads();
    for (int o = 128; o > 0; o >>= 1) { if (t < o) red[t] += red[t + o]; __syncthreads(); }
    float inv = 1.0f / red[0];
    for (int i = t; i < N2; i += 256) g_a[i] = __expf(g_logit[i] - mx) * inv;
}

__global__ void k_pool(const float* __restrict__ x2) {
    int d = threadIdx.x;
    int b = blockIdx.x;
    const float* base = x2 + (size_t)b * 32 * DM;
    float s = 0.f;
#pragma unroll 4
    for (int m = 0; m < 32; m++) s += g_a[b * 32 + m] * base[(size_t)m * DM + d];
    g_poolpart[b * DM + d] = s;
}

__global__ void k_small_final(const float* __restrict__ wf) {
    __shared__ float ps[DM];
    int d = threadIdx.x;
    float p = 0.f;
    for (int i = 0; i < 128; i++) p += g_poolpart[i * DM + d];
    ps[d] = p;
    float m2 = 0.f;
    for (int i = 0; i < 128; i++) m2 += g_part2b[i * DM + d];
    g_m2[d] = m2 * (1.0f / N2);
    __syncthreads();
    float pf = 0.f;
#pragma unroll 4
    for (int k = 0; k < DM; k++) pf += ps[k] * wf[(size_t)k * DM + d];
    g_pf[d] = pf;
}

// ------------------------- HMMA flash cross-attention (512 threads, col-split) ---------
#define QROWB 528
#define VROWB 144
#define SM_QS 0
#define SM_KS 67584
#define SM_VS 135168
#define FLASH_SMEM 208896

__device__ __forceinline__ void copy_tile_async512(uint32_t sb, int j, int buf, int tid) {
    uint32_t kd = sb + SM_KS + buf * 33792;
    const __nv_bfloat16* kg = g_Kh + (size_t)j * KT * DM;
#pragma unroll
    for (int i = 0; i < 4; i++) {
        int c = tid + i * 512;
        int r = c >> 5, q = c & 31;
        cp16(kd + r * QROWB + q * 16, kg + r * DM + q * 8);
    }
    uint32_t vd = sb + SM_VS + buf * 36864;
    const __nv_bfloat16* vg = g_VTh + (size_t)j * KT;
#pragma unroll
    for (int i = 0; i < 4; i++) {
        int c = tid + i * 512;
        int r = c >> 3, q = c & 7;
        cp16(vd + r * VROWB + q * 16, vg + (size_t)r * N2 + q * 8);
    }
}

__global__ __launch_bounds__(512, 1) void k_flash_hmma() {
    extern __shared__ char sm[];
    const int tid = threadIdx.x, warp = tid >> 5, lane = tid & 31;
    const int qt = blockIdx.x;
    const uint32_t sb = smem_u32(sm);

    {
        const uint4* src = (const uint4*)(g_Qh + (size_t)qt * 128 * DM);
#pragma unroll
        for (int i = 0; i < 8; i++) {
            int c = tid + i * 512;
            int r = c >> 5, q = c & 31;
            *(uint4*)(sm + SM_QS + r * QROWB + q * 16) = src[r * 32 + q];
        }
    }
    copy_tile_async512(sb, 0, 0, tid);
    CP_COMMIT();

    const int mg = warp & 7;          // row group: 8 groups x 16 rows
    const int colh = warp >> 3;       // column half: 0 -> d[0:128), 1 -> d[128:256)
    const int m0 = mg * 16;
    const uint32_t lsel = (lane & 15);
    const uint32_t khalf = ((lane >> 4) << 3) * 2;
    const uint32_t qaddr0 = sb + SM_QS + (m0 + lsel) * QROWB + khalf;

    float O[16][4];
#pragma unroll
    for (int f = 0; f < 16; f++)
#pragma unroll
        for (int c = 0; c < 4; c++) O[f][c] = 0.f;
    float lsum_lo = 0.f, lsum_hi = 0.f;

    for (int j = 0; j < NKT; j++) {
        int buf = j & 1;
        if (j + 1 < NKT) copy_tile_async512(sb, j + 1, buf ^ 1, tid);
        CP_COMMIT();
        CP_WAIT1();
        __syncthreads();

        // S = Q @ K^T (computed in both column-half warps; identical values)
        float S[8][4];
#pragma unroll
        for (int f = 0; f < 8; f++)
#pragma unroll
            for (int c = 0; c < 4; c++) S[f][c] = 0.f;
        const uint32_t kbase = sb + SM_KS + buf * 33792 + lsel * QROWB + khalf;
#pragma unroll 4
        for (int ks = 0; ks < 16; ks++) {
            uint32_t a0, a1, a2, a3;
            ldsm_x4(a0, a1, a2, a3, qaddr0 + ks * 32);
#pragma unroll
            for (int ng = 0; ng < 4; ng++) {
                uint32_t b0, b1, b2, b3;
                ldsm_x4(b0, b1, b2, b3, kbase + ng * 16 * QROWB + ks * 32);
                mma16816(S[ng * 2], a0, a1, a2, a3, b0, b2);
                mma16816(S[ng * 2 + 1], a0, a1, a2, a3, b1, b3);
            }
        }
        uint32_t Pa[8][2];
#pragma unroll
        for (int f = 0; f < 8; f++) {
            float e0 = __expf(S[f][0] * 0.0625f);
            float e1 = __expf(S[f][1] * 0.0625f);
            float e2 = __expf(S[f][2] * 0.0625f);
            float e3 = __expf(S[f][3] * 0.0625f);
            lsum_lo += e0 + e1;
            lsum_hi += e2 + e3;
            Pa[f][0] = pack_bf2(e0, e1);
            Pa[f][1] = pack_bf2(e2, e3);
        }
        // O += P @ V for this warp's 128-column half
        const uint32_t vbase = sb + SM_VS + buf * 36864 + lsel * VROWB + khalf;
#pragma unroll
        for (int ks = 0; ks < 4; ks++) {
            uint32_t a0 = Pa[2 * ks][0], a1 = Pa[2 * ks][1];
            uint32_t a2 = Pa[2 * ks + 1][0], a3 = Pa[2 * ks + 1][1];
#pragma unroll
            for (int jg = 0; jg < 8; jg++) {
                uint32_t b0, b1, b2, b3;
                ldsm_x4(b0, b1, b2, b3, vbase + (colh * 8 + jg) * 16 * VROWB + ks * 32);
                mma16816(O[jg * 2], a0, a1, a2, a3, b0, b2);
                mma16816(O[jg * 2 + 1], a0, a1, a2, a3, b1, b3);
            }
        }
        __syncthreads();
    }

    lsum_lo += __shfl_xor_sync(0xffffffffu, lsum_lo, 1);
    lsum_lo += __shfl_xor_sync(0xffffffffu, lsum_lo, 2);
    lsum_hi += __shfl_xor_sync(0xffffffffu, lsum_hi, 1);
    lsum_hi += __shfl_xor_sync(0xffffffffu, lsum_hi, 2);
    float inv_lo = 1.0f / lsum_lo, inv_hi = 1.0f / lsum_hi;

    int row = qt * 128 + m0 + (lane >> 2);
    float* out_lo = g_ctx + (size_t)row * DM;
    float* out_hi = out_lo + 8 * DM;
#pragma unroll
    for (int f = 0; f < 16; f++) {
        int j0 = colh * 128 + f * 8 + (lane & 3) * 2;
        *(float2*)(out_lo + j0) = make_float2(O[f][0] * inv_lo, O[f][1] * inv_lo);
        *(float2*)(out_hi + j0) = make_float2(O[f][2] * inv_hi, O[f][3] * inv_hi);
    }
}

// ------------------------- fp32 dual GEMM + combine (R7-verified) -------------------------
__global__ __launch_bounds__(256) void k_combine(
    const float* __restrict__ x1, const float* __restrict__ wo,
    const float* __restrict__ w1m, const float* __restrict__ b1,
    const float* __restrict__ g1v, float* __restrict__ out)
{
    __shared__ float A0s[32][65], A1s[32][65];
    __shared__ float W0s[32][64], W1s[32][64];
    const int tid = threadIdx.x, tx = tid & 15, ty = tid >> 4;
    const int r0 = blockIdx.y * 64, n0 = blockIdx.x * 64;
    float acc0[4][4], acc1[4][4];
#pragma unroll
    for (int i = 0; i < 4; i++)
#pragma unroll
        for (int j = 0; j < 4; j++) { acc0[i][j] = 0.f; acc1[i][j] = 0.f; }
    for (int kc = 0; kc < DM; kc += 32) {
#pragma unroll
        for (int it = 0; it < 2; it++) {
            int idx = tid + it * 256;
            int m = idx >> 3, q = idx & 7;
            float4 v0 = *(const float4*)(g_ctx + (size_t)(r0 + m) * DM + kc + q * 4);
            A0s[q * 4 + 0][m] = v0.x; A0s[q * 4 + 1][m] = v0.y;
            A0s[q * 4 + 2][m] = v0.z; A0s[q * 4 + 3][m] = v0.w;
            float4 v1 = *(const float4*)(x1 + (size_t)(r0 + m) * DM + kc + q * 4);
            float rs = g_r1[r0 + m];
            A1s[q * 4 + 0][m] = v1.x * rs * g1v[kc + q * 4 + 0];
            A1s[q * 4 + 1][m] = v1.y * rs * g1v[kc + q * 4 + 1];
            A1s[q * 4 + 2][m] = v1.z * rs * g1v[kc + q * 4 + 2];
            A1s[q * 4 + 3][m] = v1.w * rs * g1v[kc + q * 4 + 3];
        }
#pragma unroll
        for (int it = 0; it < 2; it++) {
            int idx = tid + it * 256;
            int kr = idx >> 4, q = idx & 15;
            *(float4*)&W0s[kr][q * 4] = *(const float4*)(wo + (size_t)(kc + kr) * DM + n0 + q * 4);
            *(float4*)&W1s[kr][q * 4] = *(const float4*)(w1m + (size_t)(kc + kr) * DM + n0 + q * 4);
        }
        __syncthreads();
#pragma unroll
        for (int kk = 0; kk < 32; kk++) {
            float a0[4], a1[4];
#pragma unroll
            for (int i = 0; i < 4; i++) { a0[i] = A0s[kk][ty * 4 + i]; a1[i] = A1s[kk][ty * 4 + i]; }
            float4 b04 = *(const float4*)&W0s[kk][tx * 4];
            float4 b14 = *(const float4*)&W1s[kk][tx * 4];
            float b0[4] = { b04.x, b04.y, b04.z, b04.w };
            float b1r[4] = { b14.x, b14.y, b14.z, b14.w };
#pragma unroll
            for (int i = 0; i < 4; i++)
#pragma unroll
                for (int j = 0; j < 4; j++) { acc0[i][j] += a0[i] * b0[j]; acc1[i][j] += a1[i] * b1r[j]; }
        }
        __syncthreads();
    }
    float wv0 = g_w[0], wv1 = g_w[1], wv2 = g_w[2], wv3 = g_w[3], inv = g_invns;
#pragma unroll
    for (int i = 0; i < 4; i++) {
        int row = r0 + ty * 4 + i;
#pragma unroll
        for (int j = 0; j < 4; j++) {
            int col = n0 + tx * 4 + j;
            float xv = x1[(size_t)row * DM + col];
            float sv = acc1[i][j] + b1[col];
            sv = sv > 0.f ? sv : (__expf(sv) - 1.f);
            float o = inv * (wv0 * (xv + acc0[i][j])
                           + wv1 * (sv + g_m2[col])
                           + wv2 * (xv + g_pf[col])
                           + wv3 * xv);
            out[(size_t)row * DM + col] = o;
        }
    }
}

// ------------------------- launcher -------------------------
extern "C" void kernel_launch(void* const* d_in, const int* in_sizes, int n_in,
                              void* d_out, int out_size) {
    (void)in_sizes; (void)n_in; (void)out_size;
    const float* x1     = (const float*)d_in[0];
    const float* x2     = (const float*)d_in[1];
    const float* sim    = (const float*)d_in[2];
    const float* gates  = (const float*)d_in[3];
    const float* g1v    = (const float*)d_in[4];
    const float* g2v    = (const float*)d_in[5];
    const float* snn_w1 = (const float*)d_in[6];
    const float* snn_b1 = (const float*)d_in[7];
    const float* snn_w2 = (const float*)d_in[8];
    const float* snn_b2 = (const float*)d_in[9];
    const float* wq     = (const float*)d_in[10];
    const float* wk     = (const float*)d_in[11];
    const float* wv     = (const float*)d_in[12];
    const float* wo     = (const float*)d_in[13];
    const float* va     = (const float*)d_in[14];
    const float* ua     = (const float*)d_in[15];
    const float* wa     = (const float*)d_in[16];
    const float* wf     = (const float*)d_in[17];
    float* out = (float*)d_out;

    cudaFuncSetAttribute(k_flash_hmma, cudaFuncAttributeMaxDynamicSharedMemorySize, FLASH_SMEM);
    cudaFuncSetAttribute(k_hgemm, cudaFuncAttributeMaxDynamicSharedMemorySize, HG_SMEM);

    // norms + gate (wide-grid reductions)
    k_rownorm<<<N1 / 8, 256>>>(x1, 0);
    k_rownorm<<<N2 / 8, 256>>>(x2, 1);
    k_colsum<<<256, 256>>>(x1, 64, 0);
    k_colsum<<<128, 256>>>(x2, 32, 1);
    k_gate<<<1, 256>>>(sim, gates);

    // bf16 conversions
    k_cvt_x<<<(N1 * DM) / 2048, 256>>>(x1, g_x1h, nullptr, nullptr);
    k_cvt_x<<<(N2 * DM) / 2048, 256>>>(x2, g_x2h, nullptr, nullptr);
    k_cvt_x<<<(N2 * DM) / 2048, 256>>>(x2, g_x2rh, g_r2, g2v);
    k_cvt_wt<<<256, 256>>>(wq, g_wqt);
    k_cvt_wt<<<256, 256>>>(wk, g_wkt);
    k_cvt_wt<<<256, 256>>>(wv, g_wvt);
    k_cvt_wt<<<256, 256>>>(snn_w2, g_w2t);

    // projections (HMMA, verified)
    k_hgemm<<<dim3(2, N1 / 128), 256, HG_SMEM>>>(g_x1h, g_wqt, nullptr, 0);
    k_hgemm<<<dim3(2, N2 / 128), 256, HG_SMEM>>>(g_x2h, g_wkt, nullptr, 1);
    k_hgemm<<<dim3(2, N2 / 128), 256, HG_SMEM>>>(g_x2h, g_wvt, nullptr, 2);
    k_hgemm<<<dim3(2, N2 / 128), 256, HG_SMEM>>>(g_x2rh, g_w2t, snn_b2, 3);
    k_cvt_tr<<<dim3(N2 / 64, DM / 64), 256>>>();

    // DAMISL + snn2 mean (wide grids)
    k_colsum<<<128, 256>>>(nullptr, 32, 2);
    k_hlogit<<<N2 / 64, 256>>>(x2, va, ua, wa);
    k_attnnorm<<<1, 256>>>();
    k_pool<<<128, 256>>>(x2);
    k_small_final<<<1, 256>>>(wf);

    // attention (512 threads, column-split warps)
    k_flash_hmma<<<N1 / 128, 512, FLASH_SMEM>>>();

    // combine (fp32, R7-verified)
    k_combine<<<dim3(4, N1 / 64), 256>>>(x1, wo, snn_w1, snn_b1, g1v, out);
}

// round 11
// speedup vs baseline: 1.1195x; 1.1195x over previous
#include <cuda_runtime.h>
#include <cuda_bf16.h>
#include <math.h>
#include <stdint.h>
#include <stddef.h>

#define N1 16384
#define N2 4096
#define DM 256
#define ATTD 128
#define NE 4
#define KT 64
#define NKT (N2 / KT)

// ------------------------- static device scratch -------------------------
__device__ float g_ctx[N1 * DM];
__device__ float g_Vp[N2 * DM];
__device__ float g_snn2[N2 * DM];
__device__ float g_part1[256 * DM];
__device__ float g_part2[128 * DM];
__device__ float g_part2b[128 * DM];
__device__ float g_poolpart[128 * DM];
__device__ float g_logit[N2];
__device__ float g_a[N2];
__device__ float g_r1[N1];
__device__ float g_r2[N2];
__device__ float g_w[NE];
__device__ float g_invns;
__device__ float g_m2[DM];
__device__ float g_pf[DM];
// bf16 operands
__device__ __nv_bfloat16 g_Qh[N1 * DM];
__device__ __nv_bfloat16 g_Kh[N2 * DM];
__device__ __nv_bfloat16 g_VTh[DM * N2];     // [d][key]
__device__ __nv_bfloat16 g_x1h[N1 * DM];
__device__ __nv_bfloat16 g_x2h[N2 * DM];
__device__ __nv_bfloat16 g_x2rh[N2 * DM];
// transposed bf16 weights [n][k]
__device__ __nv_bfloat16 g_wqt[DM * DM];
__device__ __nv_bfloat16 g_wkt[DM * DM];
__device__ __nv_bfloat16 g_wvt[DM * DM];
__device__ __nv_bfloat16 g_w2t[DM * DM];

// ------------------------- helpers -------------------------
__device__ __forceinline__ uint32_t smem_u32(const void* p) {
    uint32_t a;
    asm("{ .reg .u64 t; cvta.to.shared.u64 t, %1; cvt.u32.u64 %0, t; }" : "=r"(a) : "l"(p));
    return a;
}
__device__ __forceinline__ uint32_t pack_bf2(float a, float b) {
    __nv_bfloat162 t = __floats2bfloat162_rn(a, b);
    return *reinterpret_cast<uint32_t*>(&t);
}
__device__ __forceinline__ void ldsm_x4(uint32_t& r0, uint32_t& r1, uint32_t& r2, uint32_t& r3, uint32_t addr) {
    asm volatile("ldmatrix.sync.aligned.m8n8.x4.shared.b16 {%0,%1,%2,%3}, [%4];"
        : "=r"(r0), "=r"(r1), "=r"(r2), "=r"(r3) : "r"(addr));
}
__device__ __forceinline__ void mma16816(float* c, uint32_t a0, uint32_t a1, uint32_t a2, uint32_t a3,
                                         uint32_t b0, uint32_t b1) {
    asm volatile("mma.sync.aligned.m16n8k16.row.col.f32.bf16.bf16.f32 "
        "{%0,%1,%2,%3}, {%4,%5,%6,%7}, {%8,%9}, {%0,%1,%2,%3};"
        : "+f"(c[0]), "+f"(c[1]), "+f"(c[2]), "+f"(c[3])
        : "r"(a0), "r"(a1), "r"(a2), "r"(a3), "r"(b0), "r"(b1));
}
__device__ __forceinline__ void cp16(uint32_t s, const void* g) {
    asm volatile("cp.async.cg.shared.global [%0], [%1], 16;" :: "r"(s), "l"(g));
}
#define CP_COMMIT() asm volatile("cp.async.commit_group;" ::: "memory")
#define CP_WAIT1()  asm volatile("cp.async.wait_group 1;" ::: "memory")

// ------------------------- row RMS norms -------------------------
__global__ void k_rownorm(const float* __restrict__ x, int which) {
    int warp = threadIdx.x >> 5, lane = threadIdx.x & 31;
    int row = blockIdx.x * 8 + warp;
    const float* p = x + (size_t)row * DM;
    float s = 0.f;
#pragma unroll
    for (int i = 0; i < 8; i++) { float v = p[lane + i * 32]; s += v * v; }
#pragma unroll
    for (int o = 16; o > 0; o >>= 1) s += __shfl_xor_sync(0xffffffffu, s, o);
    if (lane == 0) (which ? g_r2 : g_r1)[row] = rsqrtf(s * (1.0f / DM) + 1e-6f);
}

// column partial sums — wide grids (validated end-to-end in R10)
__global__ void k_colsum(const float* __restrict__ x, int rpb, int dst) {
    const float* src = x ? x : g_snn2;
    int d = threadIdx.x;
    const float* p = src + (size_t)blockIdx.x * rpb * DM + d;
    float s = 0.f;
#pragma unroll 4
    for (int i = 0; i < rpb; i++) s += p[(size_t)i * DM];
    float* o = (dst == 0) ? g_part1 : (dst == 1) ? g_part2 : g_part2b;
    o[blockIdx.x * DM + d] = s;
}

__global__ void k_gate(const float* __restrict__ sim, const float* __restrict__ gates) {
    __shared__ float red[256];
    __shared__ float sc[NE];
    int d = threadIdx.x;
    float s1 = 0.f, s2 = 0.f;
    for (int i = 0; i < 256; i++) s1 += g_part1[i * DM + d];
    for (int i = 0; i < 128; i++) s2 += g_part2[i * DM + d];
    float f = 0.5f * (s1 * (1.0f / N1) + s2 * (1.0f / N2));
    red[d] = f * f; __syncthreads();
    for (int o = 128; o > 0; o >>= 1) { if (d < o) red[d] += red[d + o]; __syncthreads(); }
    float fn = f * rsqrtf(red[0] + 1e-8f);
    for (int e = 0; e < NE; e++) {
        float sv = sim[e * DM + d];
        __syncthreads();
        red[d] = sv * sv; __syncthreads();
        for (int o = 128; o > 0; o >>= 1) { if (d < o) red[d] += red[d + o]; __syncthreads(); }
        float invn = rsqrtf(red[0] + 1e-8f);
        __syncthreads();
        red[d] = fn * sv; __syncthreads();
        for (int o = 128; o > 0; o >>= 1) { if (d < o) red[d] += red[d + o]; __syncthreads(); }
        if (d == 0) sc[e] = red[0] * invn;
    }
    __syncthreads();
    if (d == 0) {
        float s[NE] = { sc[0], sc[1], sc[2], sc[3] };
        int am = 0;
        for (int e = 1; e < NE; e++) if (s[e] > s[am]) am = e;
        float second = -INFINITY;
        for (int e = 0; e < NE; e++) if (e != am) second = fmaxf(second, s[e]);
        int cnt = 0;
        for (int e = 0; e < NE; e++) {
            bool keep = (s[e] >= second) && (s[e] > gates[e]);
            float w = keep ? s[e] : 0.0f;
            g_w[e] = w;
            if (w > 0.f) cnt++;
        }
        g_invns = 1.0f / fmaxf((float)cnt, 1.0f);
    }
}

// ------------------------- bf16 conversions -------------------------
__global__ void k_cvt_x(const float* __restrict__ src, __nv_bfloat16* __restrict__ dst,
                        const float* __restrict__ rms, const float* __restrict__ gv) {
    size_t i = (size_t)(blockIdx.x * 256 + threadIdx.x) * 8;
    int row = (int)(i >> 8), c0 = (int)(i & 255);
    float r = rms ? rms[row] : 1.0f;
    float4 a = *(const float4*)(src + i), b = *(const float4*)(src + i + 4);
    float g[8];
#pragma unroll
    for (int k = 0; k < 8; k++) g[k] = gv ? gv[c0 + k] : 1.0f;
    *(uint4*)(dst + i) = make_uint4(
        pack_bf2(a.x * r * g[0], a.y * r * g[1]), pack_bf2(a.z * r * g[2], a.w * r * g[3]),
        pack_bf2(b.x * r * g[4], b.y * r * g[5]), pack_bf2(b.z * r * g[6], b.w * r * g[7]));
}

__global__ void k_cvt_wt(const float* __restrict__ W, __nv_bfloat16* __restrict__ dhi) {
    int idx = blockIdx.x * 256 + threadIdx.x;
    int k = idx >> 8, n = idx & 255;
    dhi[n * DM + k] = __float2bfloat16_rn(W[k * DM + n]);
}

__global__ void k_cvt_tr() {
    __shared__ float s[64][65];
    int n0 = blockIdx.x * 64, d0 = blockIdx.y * 64;
    int tid = threadIdx.x;
#pragma unroll
    for (int i = 0; i < 16; i++) {
        int e = tid + i * 256;
        int n = e >> 6, d = e & 63;
        s[n][d] = g_Vp[(size_t)(n0 + n) * DM + d0 + d];
    }
    __syncthreads();
#pragma unroll
    for (int i = 0; i < 16; i++) {
        int e = tid + i * 256;
        int d = e >> 6, n = e & 63;
        g_VTh[(size_t)(d0 + d) * N2 + n0 + n] = __float2bfloat16_rn(s[n][d]);
    }
}

// ------------------------- HMMA projection GEMM (verified) -------------------------
#define HG_AROW 528
#define HG_WOFF 67584
#define HG_SMEM 135168

__global__ __launch_bounds__(256, 1) void k_hgemm(
    const __nv_bfloat16* __restrict__ A, const __nv_bfloat16* __restrict__ Wt,
    const float* __restrict__ bias, int mode)
{
    extern __shared__ char sm[];
    const uint32_t sb = smem_u32(sm);
    const int tid = threadIdx.x, warp = tid >> 5, lane = tid & 31;
    const int r0 = blockIdx.y * 128, nb = blockIdx.x * 128;

#pragma unroll
    for (int i = 0; i < 16; i++) {
        int c = tid + i * 256;
        int r = c >> 5, q = c & 31;
        *(uint4*)(sm + r * HG_AROW + q * 16) = *(const uint4*)(A + (size_t)(r0 + r) * DM + q * 8);
        *(uint4*)(sm + HG_WOFF + r * HG_AROW + q * 16) = *(const uint4*)(Wt + (size_t)(nb + r) * DM + q * 8);
    }
    __syncthreads();

    const int wm = warp >> 1, wn = warp & 1;
    const uint32_t lsel = lane & 15;
    const uint32_t khalf = (lane >> 4) * 16;
    const uint32_t abase = sb + (wm * 32 + lsel) * HG_AROW + khalf;
    const uint32_t bbase = sb + HG_WOFF + (wn * 64 + lsel) * HG_AROW + khalf;

    float acc[2][8][4];
#pragma unroll
    for (int m = 0; m < 2; m++)
#pragma unroll
        for (int n = 0; n < 8; n++)
#pragma unroll
            for (int c = 0; c < 4; c++) acc[m][n][c] = 0.f;

#pragma unroll 4
    for (int ks = 0; ks < 16; ks++) {
        uint32_t a[2][4];
        ldsm_x4(a[0][0], a[0][1], a[0][2], a[0][3], abase + ks * 32);
        ldsm_x4(a[1][0], a[1][1], a[1][2], a[1][3], abase + 16 * HG_AROW + ks * 32);
#pragma unroll
        for (int ng = 0; ng < 4; ng++) {
            uint32_t b0, b1, b2, b3;
            ldsm_x4(b0, b1, b2, b3, bbase + ng * 16 * HG_AROW + ks * 32);
#pragma unroll
            for (int m = 0; m < 2; m++) {
                mma16816(acc[m][ng * 2], a[m][0], a[m][1], a[m][2], a[m][3], b0, b2);
                mma16816(acc[m][ng * 2 + 1], a[m][0], a[m][1], a[m][2], a[m][3], b1, b3);
            }
        }
    }

    const int rb = r0 + wm * 32 + (lane >> 2);
    const int cb = nb + wn * 64 + (lane & 3) * 2;
#pragma unroll
    for (int m = 0; m < 2; m++)
#pragma unroll
        for (int nf = 0; nf < 8; nf++) {
            int row = rb + m * 16, col = cb + nf * 8;
            float* c = acc[m][nf];
            if (mode == 0) {
                *(uint32_t*)(g_Qh + (size_t)row * DM + col) = pack_bf2(c[0], c[1]);
                *(uint32_t*)(g_Qh + (size_t)(row + 8) * DM + col) = pack_bf2(c[2], c[3]);
            } else if (mode == 1) {
                *(uint32_t*)(g_Kh + (size_t)row * DM + col) = pack_bf2(c[0], c[1]);
                *(uint32_t*)(g_Kh + (size_t)(row + 8) * DM + col) = pack_bf2(c[2], c[3]);
            } else if (mode == 2) {
                *(float2*)(g_Vp + (size_t)row * DM + col) = make_float2(c[0], c[1]);
                *(float2*)(g_Vp + (size_t)(row + 8) * DM + col) = make_float2(c[2], c[3]);
            } else {
                float bb0 = bias[col], bb1 = bias[col + 1];
                float v0 = c[0] + bb0, v1 = c[1] + bb1, v2 = c[2] + bb0, v3 = c[3] + bb1;
                v0 = v0 > 0.f ? v0 : (__expf(v0) - 1.f);
                v1 = v1 > 0.f ? v1 : (__expf(v1) - 1.f);
                v2 = v2 > 0.f ? v2 : (__expf(v2) - 1.f);
                v3 = v3 > 0.f ? v3 : (__expf(v3) - 1.f);
                *(float2*)(g_snn2 + (size_t)row * DM + col) = make_float2(v0, v1);
                *(float2*)(g_snn2 + (size_t)(row + 8) * DM + col) = make_float2(v2, v3);
            }
        }
}

// ------------------------- DAMISL logits / softmax / pool -------------------------
__global__ __launch_bounds__(256) void k_hlogit(
    const float* __restrict__ x2, const float* __restrict__ va,
    const float* __restrict__ ua, const float* __restrict__ wa)
{
    __shared__ float Xs[32][65];
    __shared__ float Vt[32][128];
    __shared__ float Ut[32][128];
    __shared__ float was[128];
    __shared__ float red[64 * 17];
    const int tid = threadIdx.x, tx = tid & 15, ty = tid >> 4;
    const int r0 = blockIdx.x * 64;
    if (tid < 128) was[tid] = wa[tid];
    float aV[4][8], aU[4][8];
#pragma unroll
    for (int i = 0; i < 4; i++)
#pragma unroll
        for (int j = 0; j < 8; j++) { aV[i][j] = 0.f; aU[i][j] = 0.f; }
    for (int kc = 0; kc < DM; kc += 32) {
#pragma unroll
        for (int it = 0; it < 2; it++) {
            int idx = tid + it * 256;
            int m = idx >> 3, q = idx & 7;
            float4 v = *(const float4*)(x2 + (size_t)(r0 + m) * DM + kc + q * 4);
            Xs[q * 4 + 0][m] = v.x; Xs[q * 4 + 1][m] = v.y;
            Xs[q * 4 + 2][m] = v.z; Xs[q * 4 + 3][m] = v.w;
        }
#pragma unroll
        for (int it = 0; it < 4; it++) {
            int idx = tid + it * 256;
            int kr = idx >> 5, q = idx & 31;
            *(float4*)&Vt[kr][q * 4] = *(const float4*)(va + (size_t)(kc + kr) * ATTD + q * 4);
            *(float4*)&Ut[kr][q * 4] = *(const float4*)(ua + (size_t)(kc + kr) * ATTD + q * 4);
        }
        __syncthreads();
#pragma unroll 4
        for (int kk = 0; kk < 32; kk++) {
            float a[4];
#pragma unroll
            for (int i = 0; i < 4; i++) a[i] = Xs[kk][ty * 4 + i];
            float4 v0 = *(const float4*)&Vt[kk][tx * 8];
            float4 v1 = *(const float4*)&Vt[kk][tx * 8 + 4];
            float4 u0 = *(const float4*)&Ut[kk][tx * 8];
            float4 u1 = *(const float4*)&Ut[kk][tx * 8 + 4];
            float vb[8] = { v0.x, v0.y, v0.z, v0.w, v1.x, v1.y, v1.z, v1.w };
            float ub[8] = { u0.x, u0.y, u0.z, u0.w, u1.x, u1.y, u1.z, u1.w };
#pragma unroll
            for (int i = 0; i < 4; i++)
#pragma unroll
                for (int j = 0; j < 8; j++) { aV[i][j] += a[i] * vb[j]; aU[i][j] += a[i] * ub[j]; }
        }
        __syncthreads();
    }
#pragma unroll
    for (int i = 0; i < 4; i++) {
        float rp = 0.f;
#pragma unroll
        for (int j = 0; j < 8; j++) {
            float h = tanhf(aV[i][j]) * (1.0f / (1.0f + __expf(-aU[i][j])));
            rp += h * was[tx * 8 + j];
        }
        red[(ty * 4 + i) * 17 + tx] = rp;
    }
    __syncthreads();
    if (tid < 64) {
        float s = 0.f;
#pragma unroll
        for (int t = 0; t < 16; t++) s += red[tid * 17 + t];
        g_logit[r0 + tid] = s;
    }
}

__global__ void k_attnnorm() {
    __shared__ float red[256];
    int t = threadIdx.x;
    float lm = -INFINITY;
    for (int i = t; i < N2; i += 256) lm = fmaxf(lm, g_logit[i]);
    red[t] = lm; __syncthreads();
    for (int o = 128; o > 0; o >>= 1) { if (t < o) red[t] = fmaxf(red[t], red[t + o]); __syncthreads(); }
    float mx = red[0];
    __syncthreads();
    float ls = 0.f;
    for (int i = t; i < N2; i += 256) ls += __expf(g_logit[i] - mx);
    red[t] = ls; __syncthreads();
    for (int o = 128; o > 0; o >>= 1) { if (t < o) red[t] += red[t + o]; __syncthreads(); }
    float inv = 1.0f / red[0];
    for (int i = t; i < N2; i += 256) g_a[i] = __expf(g_logit[i] - mx) * inv;
}

__global__ void k_pool(const float* __restrict__ x2) {
    int d = threadIdx.x;
    int b = blockIdx.x;
    const float* base = x2 + (size_t)b * 32 * DM;
    float s = 0.f;
#pragma unroll 4
    for (int m = 0; m < 32; m++) s += g_a[b * 32 + m] * base[(size_t)m * DM + d];
    g_poolpart[b * DM + d] = s;
}

__global__ void k_small_final(const float* __restrict__ wf) {
    __shared__ float ps[DM];
    int d = threadIdx.x;
    float p = 0.f;
    for (int i = 0; i < 128; i++) p += g_poolpart[i * DM + d];
    ps[d] = p;
    float m2 = 0.f;
    for (int i = 0; i < 128; i++) m2 += g_part2b[i * DM + d];
    g_m2[d] = m2 * (1.0f / N2);
    __syncthreads();
    float pf = 0.f;
#pragma unroll 4
    for (int k = 0; k < DM; k++) pf += ps[k] * wf[(size_t)k * DM + d];
    g_pf[d] = pf;
}

// ------------------------- HMMA flash cross-attention (R7 exact, 256 threads) ----------
#define QROWB 528
#define VROWB 144
#define SM_QS 0
#define SM_KS 67584
#define SM_VS 135168
#define FLASH_SMEM 208896

__device__ __forceinline__ void copy_tile_async(uint32_t sb, int j, int buf, int tid) {
    uint32_t kd = sb + SM_KS + buf * 33792;
    const __nv_bfloat16* kg = g_Kh + (size_t)j * KT * DM;
#pragma unroll
    for (int i = 0; i < 8; i++) {
        int c = tid + i * 256;
        int r = c >> 5, q = c & 31;
        cp16(kd + r * QROWB + q * 16, kg + r * DM + q * 8);
    }
    uint32_t vd = sb + SM_VS + buf * 36864;
    const __nv_bfloat16* vg = g_VTh + (size_t)j * KT;
#pragma unroll
    for (int i = 0; i < 8; i++) {
        int c = tid + i * 256;
        int r = c >> 3, q = c & 7;
        cp16(vd + r * VROWB + q * 16, vg + (size_t)r * N2 + q * 8);
    }
}

__global__ __launch_bounds__(256, 1) void k_flash_hmma() {
    extern __shared__ char sm[];
    const int tid = threadIdx.x, warp = tid >> 5, lane = tid & 31;
    const int qt = blockIdx.x;
    const uint32_t sb = smem_u32(sm);

    {
        const uint4* src = (const uint4*)(g_Qh + (size_t)qt * 128 * DM);
#pragma unroll
        for (int i = 0; i < 16; i++) {
            int c = tid + i * 256;
            int r = c >> 5, q = c & 31;
            *(uint4*)(sm + SM_QS + r * QROWB + q * 16) = src[r * 32 + q];
        }
    }
    copy_tile_async(sb, 0, 0, tid);
    CP_COMMIT();

    const int m0 = warp * 16;
    const uint32_t lsel = (lane & 15);
    const uint32_t khalf = ((lane >> 4) << 3) * 2;
    const uint32_t qaddr0 = sb + SM_QS + (m0 + lsel) * QROWB + khalf;

    float O[32][4];
#pragma unroll
    for (int f = 0; f < 32; f++)
#pragma unroll
        for (int c = 0; c < 4; c++) O[f][c] = 0.f;
    float lsum_lo = 0.f, lsum_hi = 0.f;

    for (int j = 0; j < NKT; j++) {
        int buf = j & 1;
        if (j + 1 < NKT) copy_tile_async(sb, j + 1, buf ^ 1, tid);
        CP_COMMIT();
        CP_WAIT1();
        __syncthreads();

        float S[8][4];
#pragma unroll
        for (int f = 0; f < 8; f++)
#pragma unroll
            for (int c = 0; c < 4; c++) S[f][c] = 0.f;
        const uint32_t kbase = sb + SM_KS + buf * 33792 + lsel * QROWB + khalf;
#pragma unroll 4
        for (int ks = 0; ks < 16; ks++) {
            uint32_t a0, a1, a2, a3;
            ldsm_x4(a0, a1, a2, a3, qaddr0 + ks * 32);
#pragma unroll
            for (int ng = 0; ng < 4; ng++) {
                uint32_t b0, b1, b2, b3;
                ldsm_x4(b0, b1, b2, b3, kbase + ng * 16 * QROWB + ks * 32);
                mma16816(S[ng * 2], a0, a1, a2, a3, b0, b2);
                mma16816(S[ng * 2 + 1], a0, a1, a2, a3, b1, b3);
            }
        }
        uint32_t Pa[8][2];
#pragma unroll
        for (int f = 0; f < 8; f++) {
            float e0 = __expf(S[f][0] * 0.0625f);
            float e1 = __expf(S[f][1] * 0.0625f);
            float e2 = __expf(S[f][2] * 0.0625f);
            float e3 = __expf(S[f][3] * 0.0625f);
            lsum_lo += e0 + e1;
            lsum_hi += e2 + e3;
            Pa[f][0] = pack_bf2(e0, e1);
            Pa[f][1] = pack_bf2(e2, e3);
        }
        const uint32_t vbase = sb + SM_VS + buf * 36864 + lsel * VROWB + khalf;
#pragma unroll
        for (int ks = 0; ks < 4; ks++) {
            uint32_t a0 = Pa[2 * ks][0], a1 = Pa[2 * ks][1];
            uint32_t a2 = Pa[2 * ks + 1][0], a3 = Pa[2 * ks + 1][1];
#pragma unroll
            for (int jg = 0; jg < 16; jg++) {
                uint32_t b0, b1, b2, b3;
                ldsm_x4(b0, b1, b2, b3, vbase + jg * 16 * VROWB + ks * 32);
                mma16816(O[jg * 2], a0, a1, a2, a3, b0, b2);
                mma16816(O[jg * 2 + 1], a0, a1, a2, a3, b1, b3);
            }
        }
        __syncthreads();
    }

    lsum_lo += __shfl_xor_sync(0xffffffffu, lsum_lo, 1);
    lsum_lo += __shfl_xor_sync(0xffffffffu, lsum_lo, 2);
    lsum_hi += __shfl_xor_sync(0xffffffffu, lsum_hi, 1);
    lsum_hi += __shfl_xor_sync(0xffffffffu, lsum_hi, 2);
    float inv_lo = 1.0f / lsum_lo, inv_hi = 1.0f / lsum_hi;

    int row = qt * 128 + m0 + (lane >> 2);
    float* out_lo = g_ctx + (size_t)row * DM;
    float* out_hi = out_lo + 8 * DM;
#pragma unroll
    for (int jg = 0; jg < 32; jg++) {
        int j0 = jg * 8 + (lane & 3) * 2;
        *(float2*)(out_lo + j0) = make_float2(O[jg][0] * inv_lo, O[jg][1] * inv_lo);
        *(float2*)(out_hi + j0) = make_float2(O[jg][2] * inv_hi, O[jg][3] * inv_hi);
    }
}

// ------------------------- fp32 dual GEMM + combine (R7-verified) -------------------------
__global__ __launch_bounds__(256) void k_combine(
    const float* __restrict__ x1, const float* __restrict__ wo,
    const float* __restrict__ w1m, const float* __restrict__ b1,
    const float* __restrict__ g1v, float* __restrict__ out)
{
    __shared__ float A0s[32][65], A1s[32][65];
    __shared__ float W0s[32][64], W1s[32][64];
    const int tid = threadIdx.x, tx = tid & 15, ty = tid >> 4;
    const int r0 = blockIdx.y * 64, n0 = blockIdx.x * 64;
    float acc0[4][4], acc1[4][4];
#pragma unroll
    for (int i = 0; i < 4; i++)
#pragma unroll
        for (int j = 0; j < 4; j++) { acc0[i][j] = 0.f; acc1[i][j] = 0.f; }
    for (int kc = 0; kc < DM; kc += 32) {
#pragma unroll
        for (int it = 0; it < 2; it++) {
            int idx = tid + it * 256;
            int m = idx >> 3, q = idx & 7;
            float4 v0 = *(const float4*)(g_ctx + (size_t)(r0 + m) * DM + kc + q * 4);
            A0s[q * 4 + 0][m] = v0.x; A0s[q * 4 + 1][m] = v0.y;
            A0s[q * 4 + 2][m] = v0.z; A0s[q * 4 + 3][m] = v0.w;
            float4 v1 = *(const float4*)(x1 + (size_t)(r0 + m) * DM + kc + q * 4);
            float rs = g_r1[r0 + m];
            A1s[q * 4 + 0][m] = v1.x * rs * g1v[kc + q * 4 + 0];
            A1s[q * 4 + 1][m] = v1.y * rs * g1v[kc + q * 4 + 1];
            A1s[q * 4 + 2][m] = v1.z * rs * g1v[kc + q * 4 + 2];
            A1s[q * 4 + 3][m] = v1.w * rs * g1v[kc + q * 4 + 3];
        }
#pragma unroll
        for (int it = 0; it < 2; it++) {
            int idx = tid + it * 256;
            int kr = idx >> 4, q = idx & 15;
            *(float4*)&W0s[kr][q * 4] = *(const float4*)(wo + (size_t)(kc + kr) * DM + n0 + q * 4);
            *(float4*)&W1s[kr][q * 4] = *(const float4*)(w1m + (size_t)(kc + kr) * DM + n0 + q * 4);
        }
        __syncthreads();
#pragma unroll
        for (int kk = 0; kk < 32; kk++) {
            float a0[4], a1[4];
#pragma unroll
            for (int i = 0; i < 4; i++) { a0[i] = A0s[kk][ty * 4 + i]; a1[i] = A1s[kk][ty * 4 + i]; }
            float4 b04 = *(const float4*)&W0s[kk][tx * 4];
            float4 b14 = *(const float4*)&W1s[kk][tx * 4];
            float b0[4] = { b04.x, b04.y, b04.z, b04.w };
            float b1r[4] = { b14.x, b14.y, b14.z, b14.w };
#pragma unroll
            for (int i = 0; i < 4; i++)
#pragma unroll
                for (int j = 0; j < 4; j++) { acc0[i][j] += a0[i] * b0[j]; acc1[i][j] += a1[i] * b1r[j]; }
        }
        __syncthreads();
    }
    float wv0 = g_w[0], wv1 = g_w[1], wv2 = g_w[2], wv3 = g_w[3], inv = g_invns;
#pragma unroll
    for (int i = 0; i < 4; i++) {
        int row = r0 + ty * 4 + i;
#pragma unroll
        for (int j = 0; j < 4; j++) {
            int col = n0 + tx * 4 + j;
            float xv = x1[(size_t)row * DM + col];
            float sv = acc1[i][j] + b1[col];
            sv = sv > 0.f ? sv : (__expf(sv) - 1.f);
            float o = inv * (wv0 * (xv + acc0[i][j])
                           + wv1 * (sv + g_m2[col])
                           + wv2 * (xv + g_pf[col])
                           + wv3 * xv);
            out[(size_t)row * DM + col] = o;
        }
    }
}

// ------------------------- launcher -------------------------
extern "C" void kernel_launch(void* const* d_in, const int* in_sizes, int n_in,
                              void* d_out, int out_size) {
    (void)in_sizes; (void)n_in; (void)out_size;
    const float* x1     = (const float*)d_in[0];
    const float* x2     = (const float*)d_in[1];
    const float* sim    = (const float*)d_in[2];
    const float* gates  = (const float*)d_in[3];
    const float* g1v    = (const float*)d_in[4];
    const float* g2v    = (const float*)d_in[5];
    const float* snn_w1 = (const float*)d_in[6];
    const float* snn_b1 = (const float*)d_in[7];
    const float* snn_w2 = (const float*)d_in[8];
    const float* snn_b2 = (const float*)d_in[9];
    const float* wq     = (const float*)d_in[10];
    const float* wk     = (const float*)d_in[11];
    const float* wv     = (const float*)d_in[12];
    const float* wo     = (const float*)d_in[13];
    const float* va     = (const float*)d_in[14];
    const float* ua     = (const float*)d_in[15];
    const float* wa     = (const float*)d_in[16];
    const float* wf     = (const float*)d_in[17];
    float* out = (float*)d_out;

    cudaFuncSetAttribute(k_flash_hmma, cudaFuncAttributeMaxDynamicSharedMemorySize, FLASH_SMEM);
    cudaFuncSetAttribute(k_hgemm, cudaFuncAttributeMaxDynamicSharedMemorySize, HG_SMEM);

    // norms + gate (wide-grid reductions, R10-validated)
    k_rownorm<<<N1 / 8, 256>>>(x1, 0);
    k_rownorm<<<N2 / 8, 256>>>(x2, 1);
    k_colsum<<<256, 256>>>(x1, 64, 0);
    k_colsum<<<128, 256>>>(x2, 32, 1);
    k_gate<<<1, 256>>>(sim, gates);

    // bf16 conversions
    k_cvt_x<<<(N1 * DM) / 2048, 256>>>(x1, g_x1h, nullptr, nullptr);
    k_cvt_x<<<(N2 * DM) / 2048, 256>>>(x2, g_x2h, nullptr, nullptr);
    k_cvt_x<<<(N2 * DM) / 2048, 256>>>(x2, g_x2rh, g_r2, g2v);
    k_cvt_wt<<<256, 256>>>(wq, g_wqt);
    k_cvt_wt<<<256, 256>>>(wk, g_wkt);
    k_cvt_wt<<<256, 256>>>(wv, g_wvt);
    k_cvt_wt<<<256, 256>>>(snn_w2, g_w2t);

    // projections (HMMA, verified)
    k_hgemm<<<dim3(2, N1 / 128), 256, HG_SMEM>>>(g_x1h, g_wqt, nullptr, 0);
    k_hgemm<<<dim3(2, N2 / 128), 256, HG_SMEM>>>(g_x2h, g_wkt, nullptr, 1);
    k_hgemm<<<dim3(2, N2 / 128), 256, HG_SMEM>>>(g_x2h, g_wvt, nullptr, 2);
    k_hgemm<<<dim3(2, N2 / 128), 256, HG_SMEM>>>(g_x2rh, g_w2t, snn_b2, 3);
    k_cvt_tr<<<dim3(N2 / 64, DM / 64), 256>>>();

    // DAMISL + snn2 mean (wide grids, R10-validated)
    k_colsum<<<128, 256>>>(nullptr, 32, 2);
    k_hlogit<<<N2 / 64, 256>>>(x2, va, ua, wa);
    k_attnnorm<<<1, 256>>>();
    k_pool<<<128, 256>>>(x2);
    k_small_final<<<1, 256>>>(wf);

    // attention (R7-exact, 256 threads, no spills)
    k_flash_hmma<<<N1 / 128, 256, FLASH_SMEM>>>();

    // combine (fp32, R7-verified)
    k_combine<<<dim3(4, N1 / 64), 256>>>(x1, wo, snn_w1, snn_b1, g1v, out);
}